// round 1
// baseline (speedup 1.0000x reference)
#include <cuda_runtime.h>

// SinglePopEncoder: out[b, c*64+p] = heaviside(beta[c]*mem + (x[b,c]*W[c,p]+b[c,p]) - heaviside(mem-thr[c])*thr[c] - thr[c])
// B=262144, C=6, P=64. HBM-bound streaming: 402MB mem read + 402MB out write.

__constant__ float c_beta[6] = {0.9f, 0.85f, 0.9f, 0.85f, 0.9f, 0.85f};
__constant__ float c_thr[6]  = {1.0f, 1.0f, 1.0f, 1.0f, 1.0f, 1.0f};

#define CP4 96   // C*P/4 float4 per batch row
#define P4  16   // P/4 float4 per (b,c)

__global__ void __launch_bounds__(256, 8) spe_kernel(
    const float* __restrict__ x,     // [B, 6]
    const float* __restrict__ W,     // [6, 64]
    const float* __restrict__ bias,  // [6, 64]
    const float* __restrict__ mem,   // [B, 6, 64]
    float* __restrict__ out,         // [B, 384]
    int total4)
{
    int i = blockIdx.x * blockDim.x + threadIdx.x;
    if (i >= total4) return;

    int b  = i / CP4;            // batch row
    int r  = i - b * CP4;        // float4 index within row [0,96)
    int c  = r >> 4;             // channel [0,6)
    int p4 = r & (P4 - 1);       // float4 index within channel [0,16)

    float xv   = __ldg(&x[b * 6 + c]);
    float beta = c_beta[c];
    float thr  = c_thr[c];

    const float4* Wv = reinterpret_cast<const float4*>(W    + c * 64) + p4;
    const float4* Bv = reinterpret_cast<const float4*>(bias + c * 64) + p4;
    const float4* Mv = reinterpret_cast<const float4*>(mem)  + i;

    float4 w  = __ldg(Wv);
    float4 bv = __ldg(Bv);
    float4 m  = __ldg(Mv);

    float4 o;
    {
        float reset = (m.x > thr) ? thr : 0.0f;
        float mn = fmaf(beta, m.x, fmaf(xv, w.x, bv.x)) - reset;
        o.x = (mn > thr) ? 1.0f : 0.0f;
    }
    {
        float reset = (m.y > thr) ? thr : 0.0f;
        float mn = fmaf(beta, m.y, fmaf(xv, w.y, bv.y)) - reset;
        o.y = (mn > thr) ? 1.0f : 0.0f;
    }
    {
        float reset = (m.z > thr) ? thr : 0.0f;
        float mn = fmaf(beta, m.z, fmaf(xv, w.z, bv.z)) - reset;
        o.z = (mn > thr) ? 1.0f : 0.0f;
    }
    {
        float reset = (m.w > thr) ? thr : 0.0f;
        float mn = fmaf(beta, m.w, fmaf(xv, w.w, bv.w)) - reset;
        o.w = (mn > thr) ? 1.0f : 0.0f;
    }

    reinterpret_cast<float4*>(out)[i] = o;
}

extern "C" void kernel_launch(void* const* d_in, const int* in_sizes, int n_in,
                              void* d_out, int out_size)
{
    const float* x    = (const float*)d_in[0];   // [B, 6]
    const float* W    = (const float*)d_in[1];   // [6, 64]
    const float* bias = (const float*)d_in[2];   // [6, 64]
    const float* mem  = (const float*)d_in[3];   // [B, 6, 64]
    float* out = (float*)d_out;

    int total4 = out_size / 4;                   // 25,165,824
    int threads = 256;
    int blocks = (total4 + threads - 1) / threads;

    spe_kernel<<<blocks, threads>>>(x, W, bias, mem, out, total4);
}

// round 2
// speedup vs baseline: 1.0841x; 1.0841x over previous
#include <cuda_runtime.h>

// SinglePopEncoder: out[b, c*64+p] = heaviside(beta[c]*mem_new - thr)
//   mem_new = beta[c]*mem + (x[b,c]*W[c,p] + b[c,p]) - heaviside(mem - thr[c])*thr[c]
// B=262144, C=6, P=64. HBM-bound: 402MB mem read + 402MB out write.
// R2: 4x float4 per thread (MLP=4 on DRAM stream) + streaming cache hints.

__constant__ float c_beta[6] = {0.9f, 0.85f, 0.9f, 0.85f, 0.9f, 0.85f};
__constant__ float c_thr[6]  = {1.0f, 1.0f, 1.0f, 1.0f, 1.0f, 1.0f};

#define CP4   96   // C*P/4 float4 per batch row
#define P4    16   // P/4 float4 per (b,c)
#define VPT   4    // float4 per thread
#define TPB   256

__device__ __forceinline__ float4 spe_compute(float4 m, float4 w, float4 bv,
                                              float xv, float beta, float thr)
{
    float4 o;
    {
        float reset = (m.x > thr) ? thr : 0.0f;
        float mn = fmaf(beta, m.x, fmaf(xv, w.x, bv.x)) - reset;
        o.x = (mn > thr) ? 1.0f : 0.0f;
    }
    {
        float reset = (m.y > thr) ? thr : 0.0f;
        float mn = fmaf(beta, m.y, fmaf(xv, w.y, bv.y)) - reset;
        o.y = (mn > thr) ? 1.0f : 0.0f;
    }
    {
        float reset = (m.z > thr) ? thr : 0.0f;
        float mn = fmaf(beta, m.z, fmaf(xv, w.z, bv.z)) - reset;
        o.z = (mn > thr) ? 1.0f : 0.0f;
    }
    {
        float reset = (m.w > thr) ? thr : 0.0f;
        float mn = fmaf(beta, m.w, fmaf(xv, w.w, bv.w)) - reset;
        o.w = (mn > thr) ? 1.0f : 0.0f;
    }
    return o;
}

__global__ void __launch_bounds__(TPB, 8) spe_kernel(
    const float* __restrict__ x,     // [B, 6]
    const float* __restrict__ W,     // [6, 64]
    const float* __restrict__ bias,  // [6, 64]
    const float* __restrict__ mem,   // [B, 6, 64]
    float* __restrict__ out,         // [B, 384]
    int total4)
{
    int base = blockIdx.x * (TPB * VPT) + threadIdx.x;

    int   idx[VPT];
    float4 m[VPT];

    // Batch all DRAM-tier loads first: MLP=4 on the mem stream.
    #pragma unroll
    for (int v = 0; v < VPT; v++) {
        idx[v] = base + v * TPB;
        if (idx[v] < total4)
            m[v] = __ldcs(reinterpret_cast<const float4*>(mem) + idx[v]);
    }

    #pragma unroll
    for (int v = 0; v < VPT; v++) {
        int i = idx[v];
        if (i >= total4) continue;

        int b  = i / CP4;
        int r  = i - b * CP4;
        int c  = r >> 4;           // channel [0,6)
        int p4 = r & (P4 - 1);     // float4 within channel

        float xv   = __ldg(&x[b * 6 + c]);
        float beta = c_beta[c];
        float thr  = c_thr[c];

        float4 w  = __ldg(reinterpret_cast<const float4*>(W    + c * 64) + p4);
        float4 bv = __ldg(reinterpret_cast<const float4*>(bias + c * 64) + p4);

        float4 o = spe_compute(m[v], w, bv, xv, beta, thr);
        __stcs(reinterpret_cast<float4*>(out) + i, o);
    }
}

extern "C" void kernel_launch(void* const* d_in, const int* in_sizes, int n_in,
                              void* d_out, int out_size)
{
    const float* x    = (const float*)d_in[0];   // [B, 6]
    const float* W    = (const float*)d_in[1];   // [6, 64]
    const float* bias = (const float*)d_in[2];   // [6, 64]
    const float* mem  = (const float*)d_in[3];   // [B, 6, 64]
    float* out = (float*)d_out;

    int total4 = out_size / 4;                   // 25,165,824
    int blocks = (total4 + TPB * VPT - 1) / (TPB * VPT);  // 24576

    spe_kernel<<<blocks, TPB>>>(x, W, bias, mem, out, total4);
}